// round 1
// baseline (speedup 1.0000x reference)
#include <cuda_runtime.h>
#include <math.h>

#define LOG_SQRT_2PI 0.918938533204672742f   // 0.5*log(2*pi)

__device__ float g_prior;

// ---------------------------------------------------------------------------
// Kernel 1: prior. Single block, 1024 threads, double accumulation.
// Replicates _expected_mu branch logic exactly (branches mutually exclusive).
// ---------------------------------------------------------------------------
__global__ void prior_kernel(const float* __restrict__ pred,
                             const float* __restrict__ sig,
                             int B) {
    double acc = 0.0;
    for (int b = threadIdx.x; b < B; b += blockDim.x) {
        const float* p = pred + (size_t)b * 7;
        float O2 = p[0], N2 = p[1], H2 = p[2], CO2 = p[3],
              H2O = p[4], CH4 = p[5], NH3 = p[6];

        float H = 2.f*H2 + 2.f*H2O + 3.f*NH3 + 4.f*CH4;
        float C = CO2 + CH4;
        float O = 2.f*O2 + 2.f*CO2 + H2O;
        float N = 2.f*N2 + NH3;

        float mu0=0.f, mu1=0.f, mu2=0.f, mu3=0.f, mu4=0.f, mu5=0.f, mu6=0.f;

        if (H > 2.f*O + 4.f*C) {
            if (3.f*N < H - 2.f*O - 4.f*C) {
                // branch A1: D = H - N - 2C
                float D = H - N - 2.f*C;
                mu2 = (H - 2.f*O - 4.f*C - 3.f*N) / D;
                mu4 = 2.f*O / D;
                mu5 = 2.f*C / D;
                mu6 = 2.f*N / D;
            } else {
                // branch A2: D = H + 2C + 3N + 4O
                float D = H + 2.f*C + 3.f*N + 4.f*O;
                mu1 = (3.f*N + 4.f*C + 2.f*O - H) / D;
                mu4 = 6.f*O / D;
                mu5 = 6.f*C / D;
                mu6 = (2.f*H - 8.f*C - 4.f*O) / D;
            }
        } else if (2.f*O > H + 4.f*C) {
            // branch B: D = H + 2O + 2N
            float D = H + 2.f*O + 2.f*N;
            mu0 = (2.f*O - H - 4.f*C) / D;
            mu1 = 2.f*N / D;
            mu3 = 4.f*C / D;
            mu4 = 2.f*H / D;
        } else if (fabsf(H + C + O + N - 1.0f) < 1e-3f) {
            // branch C: D1 = H + 2O + 2N, D2 = 2H + 4O + 4N
            float D1 = H + 2.f*O + 2.f*N;
            float D2 = 2.f*H + 4.f*O + 4.f*N;
            mu1 = 2.f*N / D1;
            mu3 = (2.f*O + 4.f*C - H) / D2;
            mu4 = (H + 2.f*O - 4.f*C) / D1;
            mu5 = (H - 2.f*O + 4.f*C) / D2;
        }
        // else: unclassified -> mu = 0

        float pv[7] = {O2, N2, H2, CO2, H2O, CH4, NH3};
        float mv[7] = {mu0, mu1, mu2, mu3, mu4, mu5, mu6};
        const float* s = sig + (size_t)b * 7;
        #pragma unroll
        for (int i = 0; i < 7; i++) {
            float sv = s[i];
            float d  = pv[i] - mv[i];
            acc += (double)(LOG_SQRT_2PI + logf(sv) + d*d / (2.0f*sv*sv));
        }
    }

    __shared__ double sh[1024];
    sh[threadIdx.x] = acc;
    __syncthreads();
    for (int stride = blockDim.x >> 1; stride > 0; stride >>= 1) {
        if (threadIdx.x < stride) sh[threadIdx.x] += sh[threadIdx.x + stride];
        __syncthreads();
    }
    if (threadIdx.x == 0) g_prior = (float)(sh[0] / (double)B);
}

// ---------------------------------------------------------------------------
// Kernel 2: per-row MSE likelihood + prior. One block per row.
// 256 threads, float4 loads: 4 iterations per thread over 4096 floats.
// ---------------------------------------------------------------------------
__global__ void lik_kernel(const float* __restrict__ yReal,
                           const float* __restrict__ ySim,
                           float* __restrict__ out,
                           int S) {
    int b = blockIdx.x;
    const float4* r4 = (const float4*)(yReal + (size_t)b * S);
    const float4* s4 = (const float4*)(ySim  + (size_t)b * S);
    int n4 = S >> 2;

    float acc = 0.f;
    for (int i = threadIdx.x; i < n4; i += blockDim.x) {
        float4 a = r4[i];
        float4 c = s4[i];
        float d0 = a.x - c.x;
        float d1 = a.y - c.y;
        float d2 = a.z - c.z;
        float d3 = a.w - c.w;
        acc += d0*d0 + d1*d1 + d2*d2 + d3*d3;
    }

    // warp reduce
    #pragma unroll
    for (int off = 16; off > 0; off >>= 1)
        acc += __shfl_down_sync(0xFFFFFFFFu, acc, off);

    __shared__ float warp_sum[8];
    int lane = threadIdx.x & 31;
    int wid  = threadIdx.x >> 5;
    if (lane == 0) warp_sum[wid] = acc;
    __syncthreads();

    if (wid == 0) {
        float v = (lane < (blockDim.x >> 5)) ? warp_sum[lane] : 0.f;
        #pragma unroll
        for (int off = 4; off > 0; off >>= 1)
            v += __shfl_down_sync(0xFFFFFFFFu, v, off);
        if (lane == 0) {
            float mse = v / (float)S;
            out[b] = mse / (2.0f * 0.1f * 0.1f) + g_prior;
        }
    }
}

extern "C" void kernel_launch(void* const* d_in, const int* in_sizes, int n_in,
                              void* d_out, int out_size) {
    const float* predAbun   = (const float*)d_in[0];
    const float* sigmaPrior = (const float*)d_in[1];
    const float* yReal      = (const float*)d_in[2];
    const float* ySim       = (const float*)d_in[3];
    float* out = (float*)d_out;

    int B = in_sizes[0] / 7;
    int S = in_sizes[2] / B;

    prior_kernel<<<1, 1024>>>(predAbun, sigmaPrior, B);
    lik_kernel<<<B, 256>>>(yReal, ySim, out, S);
}

// round 4
// speedup vs baseline: 1.4590x; 1.4590x over previous
#include <cuda_runtime.h>
#include <math.h>

#define LOG_SQRT_2PI 0.918938533204672742f   // 0.5*log(2*pi)
#define PRIOR_BLOCKS 32

__device__ double g_prior_partial[PRIOR_BLOCKS];

// ---------------------------------------------------------------------------
// Kernel 1: prior partial sums. 32 blocks x 256 threads = 8192 threads,
// one row per thread (grid-stride for generality). Per-block double partial.
// ---------------------------------------------------------------------------
__global__ void prior_partial_kernel(const float* __restrict__ pred,
                                     const float* __restrict__ sig,
                                     int B) {
    double acc = 0.0;
    int stride = gridDim.x * blockDim.x;
    for (int b = blockIdx.x * blockDim.x + threadIdx.x; b < B; b += stride) {
        const float* p = pred + (size_t)b * 7;
        float O2 = p[0], N2 = p[1], H2 = p[2], CO2 = p[3],
              H2O = p[4], CH4 = p[5], NH3 = p[6];

        float H = 2.f*H2 + 2.f*H2O + 3.f*NH3 + 4.f*CH4;
        float C = CO2 + CH4;
        float O = 2.f*O2 + 2.f*CO2 + H2O;
        float N = 2.f*N2 + NH3;

        float mu0=0.f, mu1=0.f, mu2=0.f, mu3=0.f, mu4=0.f, mu5=0.f, mu6=0.f;

        if (H > 2.f*O + 4.f*C) {
            if (3.f*N < H - 2.f*O - 4.f*C) {
                float D = H - N - 2.f*C;                 // branch A1
                mu2 = (H - 2.f*O - 4.f*C - 3.f*N) / D;
                mu4 = 2.f*O / D;
                mu5 = 2.f*C / D;
                mu6 = 2.f*N / D;
            } else {
                float D = H + 2.f*C + 3.f*N + 4.f*O;    // branch A2
                mu1 = (3.f*N + 4.f*C + 2.f*O - H) / D;
                mu4 = 6.f*O / D;
                mu5 = 6.f*C / D;
                mu6 = (2.f*H - 8.f*C - 4.f*O) / D;
            }
        } else if (2.f*O > H + 4.f*C) {
            float D = H + 2.f*O + 2.f*N;                 // branch B
            mu0 = (2.f*O - H - 4.f*C) / D;
            mu1 = 2.f*N / D;
            mu3 = 4.f*C / D;
            mu4 = 2.f*H / D;
        } else if (fabsf(H + C + O + N - 1.0f) < 1e-3f) {
            float D1 = H + 2.f*O + 2.f*N;                // branch C
            float D2 = 2.f*H + 4.f*O + 4.f*N;
            mu1 = 2.f*N / D1;
            mu3 = (2.f*O + 4.f*C - H) / D2;
            mu4 = (H + 2.f*O - 4.f*C) / D1;
            mu5 = (H - 2.f*O + 4.f*C) / D2;
        }
        // else: unclassified -> mu = 0

        float pv[7] = {O2, N2, H2, CO2, H2O, CH4, NH3};
        float mv[7] = {mu0, mu1, mu2, mu3, mu4, mu5, mu6};
        const float* s = sig + (size_t)b * 7;
        float row = 0.f;
        #pragma unroll
        for (int i = 0; i < 7; i++) {
            float sv = s[i];
            float d  = pv[i] - mv[i];
            row += LOG_SQRT_2PI + logf(sv) + d*d / (2.0f*sv*sv);
        }
        acc += (double)row;
    }

    __shared__ double sh[256];
    sh[threadIdx.x] = acc;
    __syncthreads();
    for (int st = blockDim.x >> 1; st > 0; st >>= 1) {
        if (threadIdx.x < st) sh[threadIdx.x] += sh[threadIdx.x + st];
        __syncthreads();
    }
    if (threadIdx.x == 0) g_prior_partial[blockIdx.x] = sh[0];
}

// ---------------------------------------------------------------------------
// Kernel 2: per-row MSE likelihood + prior combine. One block per row,
// 256 threads, streaming float4 loads, 4x unrolled fast path.
// ---------------------------------------------------------------------------
__global__ void lik_kernel(const float* __restrict__ yReal,
                           const float* __restrict__ ySim,
                           float* __restrict__ out,
                           int S, int B) {
    int b = blockIdx.x;
    const float4* r4 = (const float4*)(yReal + (size_t)b * S);
    const float4* s4 = (const float4*)(ySim  + (size_t)b * S);
    int n4 = S >> 2;

    float acc = 0.f;
    int i = threadIdx.x;
    int step = blockDim.x;

    // fast path: 4 pairs of float4 per trip, loads front-batched for MLP
    for (; i + 3 * step < n4; i += 4 * step) {
        float4 a0 = __ldcs(r4 + i);
        float4 a1 = __ldcs(r4 + i + step);
        float4 a2 = __ldcs(r4 + i + 2 * step);
        float4 a3 = __ldcs(r4 + i + 3 * step);
        float4 c0 = __ldcs(s4 + i);
        float4 c1 = __ldcs(s4 + i + step);
        float4 c2 = __ldcs(s4 + i + 2 * step);
        float4 c3 = __ldcs(s4 + i + 3 * step);

        float t0 = (a0.x-c0.x)*(a0.x-c0.x) + (a0.y-c0.y)*(a0.y-c0.y)
                 + (a0.z-c0.z)*(a0.z-c0.z) + (a0.w-c0.w)*(a0.w-c0.w);
        float t1 = (a1.x-c1.x)*(a1.x-c1.x) + (a1.y-c1.y)*(a1.y-c1.y)
                 + (a1.z-c1.z)*(a1.z-c1.z) + (a1.w-c1.w)*(a1.w-c1.w);
        float t2 = (a2.x-c2.x)*(a2.x-c2.x) + (a2.y-c2.y)*(a2.y-c2.y)
                 + (a2.z-c2.z)*(a2.z-c2.z) + (a2.w-c2.w)*(a2.w-c2.w);
        float t3 = (a3.x-c3.x)*(a3.x-c3.x) + (a3.y-c3.y)*(a3.y-c3.y)
                 + (a3.z-c3.z)*(a3.z-c3.z) + (a3.w-c3.w)*(a3.w-c3.w);
        acc += (t0 + t1) + (t2 + t3);
    }
    // tail
    for (; i < n4; i += step) {
        float4 a = __ldcs(r4 + i);
        float4 c = __ldcs(s4 + i);
        float d0 = a.x - c.x, d1 = a.y - c.y, d2 = a.z - c.z, d3 = a.w - c.w;
        acc += d0*d0 + d1*d1 + d2*d2 + d3*d3;
    }

    // warp reduce
    #pragma unroll
    for (int off = 16; off > 0; off >>= 1)
        acc += __shfl_down_sync(0xFFFFFFFFu, acc, off);

    __shared__ float warp_sum[8];
    int lane = threadIdx.x & 31;
    int wid  = threadIdx.x >> 5;
    if (lane == 0) warp_sum[wid] = acc;
    __syncthreads();

    if (wid == 0) {
        float v = (lane < (blockDim.x >> 5)) ? warp_sum[lane] : 0.f;
        #pragma unroll
        for (int off = 4; off > 0; off >>= 1)
            v += __shfl_down_sync(0xFFFFFFFFu, v, off);

        // combine prior partials (32 doubles, L2-resident)
        double pp = (lane < PRIOR_BLOCKS) ? g_prior_partial[lane] : 0.0;
        #pragma unroll
        for (int off = 16; off > 0; off >>= 1)
            pp += __shfl_down_sync(0xFFFFFFFFu, pp, off);

        if (lane == 0) {
            float mse = v / (float)S;
            out[b] = mse * 50.0f + (float)(pp / (double)B);  // 1/(2*0.1^2)=50
        }
    }
}

extern "C" void kernel_launch(void* const* d_in, const int* in_sizes, int n_in,
                              void* d_out, int out_size) {
    const float* predAbun   = (const float*)d_in[0];
    const float* sigmaPrior = (const float*)d_in[1];
    const float* yReal      = (const float*)d_in[2];
    const float* ySim       = (const float*)d_in[3];
    float* out = (float*)d_out;

    int B = in_sizes[0] / 7;
    int S = in_sizes[2] / B;

    prior_partial_kernel<<<PRIOR_BLOCKS, 256>>>(predAbun, sigmaPrior, B);
    lik_kernel<<<B, 256>>>(yReal, ySim, out, S, B);
}